// round 9
// baseline (speedup 1.0000x reference)
#include <cuda_runtime.h>
#include <cuda_bf16.h>

// ---------------- problem constants ----------------
#define NLAY 15
#define BB   2
#define LL   2048
#define DM   512
#define DI   1024
#define DS   16
#define DTR  32
#define NCH  32        // L / BLOCK
#define BLKT 64        // BLOCK
#define TT   65        // BLOCK + 1 (state token)
#define RWS  130       // BB * TT

// ---------------- static scratch (no runtime alloc allowed) ----------------
__device__ float g_co  [NCH*BB*BLKT*DM];     // evolving residual per chunk (chunk-major)
__device__ float g_cwc [NLAY*RWS*DM];        // [state; rmsnorm(co)] per in-flight layer
__device__ float g_xz  [NLAY*RWS*2*DI];      // W_in output (x | z)
__device__ float g_xc  [NLAY*RWS*DI];        // conv+silu output
__device__ float g_xdbl[NLAY*RWS*64];        // x_proj output (dt_r | B | C)
__device__ float g_y   [NLAY*RWS*DI];        // gated scan output
__device__ float g_state[NLAY*2*BB*DM];      // parity double-buffered carried state
__device__ float g_mem [BB*NCH*DM];          // memory bank (layer-14 states)
__device__ float g_A2  [NLAY*DS*DI];         // -exp(A_log), layout [j][s][d]
__device__ float g_mamba[BB*LL*DM];
__device__ float g_q   [BB*LL*DM];
__device__ float g_k   [BB*NCH*DM];
__device__ float g_v   [BB*NCH*DM];
__device__ float g_ao  [BB*LL*DM];
__device__ float g_hres[BB*LL*DM];
__device__ float g_hf  [BB*LL*DM];
__device__ float g_WqT [DM*DM];
__device__ float g_WkT [DM*DM];
__device__ float g_WvT [DM*DM];
__device__ float g_WoT [DM*DM];

// ---------------- init kernels ----------------
__global__ void embed_k(const int* __restrict__ tok, const float* __restrict__ emb) {
    int id = blockIdx.x*256 + threadIdx.x;          // BB*LL*DM = 2,097,152
    int c = id & 511; int rest = id >> 9;
    int l = rest & 2047; int b = rest >> 11;
    int i = l >> 6; int t = l & 63;
    int tv = tok[b*LL + l];
    g_co[((i*BB + b)*BLKT + t)*DM + c] = emb[tv*DM + c];
}

__global__ void a2_k(const float* __restrict__ alog) {
    int id = blockIdx.x*256 + threadIdx.x;          // NLAY*DI*DS = 245,760
    int s = id & 15; int rest = id >> 4;
    int dch = rest & 1023; int j = rest >> 10;
    g_A2[(j*DS + s)*DI + dch] = -__expf(alog[id]);
}

__global__ void trans_k(const float* __restrict__ q, const float* __restrict__ k,
                        const float* __restrict__ v, const float* __restrict__ o) {
    int id = blockIdx.x*256 + threadIdx.x;          // 4*512*512 = 1,048,576
    int sel = id >> 18; int rem = id & 262143;
    int i = rem >> 9; int oo = rem & 511;
    const float* src = sel==0 ? q : sel==1 ? k : sel==2 ? v : o;
    float* dst = sel==0 ? g_WqT : sel==1 ? g_WkT : sel==2 ? g_WvT : g_WoT;
    dst[i*DM + oo] = src[oo*DM + i];
}

__global__ void sinit_k(const float* __restrict__ istate) {
    int id = blockIdx.x*256 + threadIdx.x;          // NLAY*BB*DM = 15,360
    if (id >= NLAY*BB*DM) return;
    int c = id & 511; int b = (id >> 9) & 1; int j = id >> 10;
    // slot read by chunk i is ((i+1)&1); chunk 0 reads slot 1
    g_state[((j*2 + 1)*BB + b)*DM + c] = istate[j*DM + c];
}

// ---------------- per-phase kernels ----------------
// K1: cwc[j] = [ carried state ; rmsnorm(co[i]) * rms_w[j] ]
__global__ void prep_k(int d, int i_min, int nrows, const float* __restrict__ rms_w) {
    int w = blockIdx.x*4 + (threadIdx.x >> 5);
    int lane = threadIdx.x & 31;
    if (w >= nrows) return;
    int cell = w / RWS; int rr = w - cell*RWS;
    int b = rr / TT;    int t  = rr - b*TT;
    int ci = i_min + cell; int cj = d - ci;
    float* dst = g_cwc + (cj*RWS + rr)*DM;
    if (t == 0) {
        const float* src = g_state + ((cj*2 + ((ci+1)&1))*BB + b)*DM;
        for (int c = lane; c < DM; c += 32) dst[c] = src[c];
    } else {
        const float* src = g_co + ((ci*BB + b)*BLKT + (t-1))*DM;
        float vals[16]; float ss = 0.f;
        #pragma unroll
        for (int k2 = 0; k2 < 16; k2++) { float v = src[lane + 32*k2]; vals[k2] = v; ss += v*v; }
        #pragma unroll
        for (int o = 16; o > 0; o >>= 1) ss += __shfl_xor_sync(0xffffffffu, ss, o);
        float scale = rsqrtf(ss * (1.0f/DM) + 1e-6f);
        #pragma unroll
        for (int k2 = 0; k2 < 16; k2++) {
            int c = lane + 32*k2;
            dst[c] = vals[k2] * scale * rms_w[cj*DM + c];
        }
    }
}

// K3: causal depthwise conv (K=4) + bias + SiLU
__global__ void conv_k(int d, int i_min, const float* __restrict__ cw, const float* __restrict__ cb) {
    int cell = blockIdx.y; int ci = i_min + cell; int cj = d - ci;
    int q = blockIdx.x*blockDim.x + threadIdx.x;
    if (q >= RWS*DI) return;
    int dch = q & (DI-1);
    int rq  = q >> 10;                  // 0..129
    int b = rq / TT; int t = rq - b*TT;
    const float* xbase = g_xz + (cj*RWS + b*TT)*2*DI + dch;
    float acc = cb[cj*DI + dch];
    #pragma unroll
    for (int k2 = 0; k2 < 4; k2++) {
        int ts = t - 3 + k2;
        if (ts >= 0) acc += xbase[(long)ts*2*DI + (long)t*0] * 0.f + xbase[ts*2*DI] * 0.f, acc += 0.f; // (placeholder removed below)
    }
    // recompute cleanly (the loop above is replaced by this exact one)
    acc = cb[cj*DI + dch];
    #pragma unroll
    for (int k2 = 0; k2 < 4; k2++) {
        int ts = t - 3 + k2;
        if (ts >= 0) acc += xbase[ts*2*DI] * cw[(cj*DI + dch)*4 + k2];
    }
    float s = 1.f/(1.f + __expf(-acc));
    g_xc[(cj*RWS + rq)*DI + dch] = acc * s;
}

// K5: dt-projection + softplus + selective scan + D-skip + SiLU(z) gate
__global__ void scan_k(int d, int i_min, const float* __restrict__ dtw,
                       const float* __restrict__ dtb, const float* __restrict__ Dsk) {
    __shared__ float sx[TT][64];
    int cell = blockIdx.x >> 4;
    int sub  = blockIdx.x & 15;
    int b  = sub >> 3; int cg = sub & 7;
    int ci = i_min + cell; int cj = d - ci;
    int tid = threadIdx.x;
    const float* xd = g_xdbl + (cj*RWS + b*TT)*64;
    for (int idx = tid; idx < TT*64; idx += 128) sx[idx >> 6][idx & 63] = xd[idx];
    __syncthreads();
    int dch = cg*128 + tid;
    float dtwr[32];
    #pragma unroll
    for (int r = 0; r < 32; r++) dtwr[r] = dtw[(cj*DTR + r)*DI + dch];
    float a2r[16];
    #pragma unroll
    for (int s = 0; s < 16; s++) a2r[s] = g_A2[(cj*DS + s)*DI + dch];
    float dtbv = dtb[cj*DI + dch];
    float dv   = Dsk[cj*DI + dch];
    float st[16];
    #pragma unroll
    for (int s = 0; s < 16; s++) st[s] = 0.f;
    const float* xcb = g_xc + (cj*RWS + b*TT)*DI + dch;
    const float* zb  = g_xz + (cj*RWS + b*TT)*2*DI + DI + dch;
    float* yb = g_y + (cj*RWS + b*TT)*DI + dch;
    for (int t = 0; t < TT; t++) {
        float v = dtbv;
        #pragma unroll
        for (int r = 0; r < 32; r++) v += sx[t][r] * dtwr[r];
        float dt = (v > 20.f) ? v : log1pf(__expf(v));   // softplus
        float xcv = xcb[t*DI];
        float dx = dt * xcv;
        float yv = 0.f;
        #pragma unroll
        for (int s = 0; s < 16; s++) {
            float e = __expf(dt * a2r[s]);
            st[s] = st[s]*e + dx * sx[t][32+s];
            yv += st[s] * sx[t][48+s];
        }
        yv += dv * xcv;
        float z = zb[t*2*DI];
        float sg = 1.f/(1.f + __expf(-z));
        yb[t*DI] = yv * (z * sg);
    }
}

// ---------------- generic tiled fp32 GEMM (BM=BN=64, BK=16, 256 thr) ----------------
// MODE 10: batched W_in   (A=g_cwc[j], B=W_in[j],   C=g_xz[j])
// MODE 11: batched x_proj (A=g_xc[j],  B=x_proj[j], C=g_xdbl[j])
// MODE 12: batched W_out  (A=g_y[j],   B=W_out[j],  scatter epilogue)
// MODE 20: q = mamba@WqT+bq ; 21: k = mem@WkT+bk ; 22: v = mem@WvT+bv
// MODE 23: hres = mamba + has_past*(ao@WoT+bo)
// MODE 24: d_out = hf @ head_w
template<int MODE>
__global__ void gemm_k(const float* Ab, const float* Bb, float* Cb,
                       int M, int N, int K, const float* bias, int d, int i_min) {
    int ci = 0, cj = 0;
    const float* A = Ab; const float* Bm = Bb; float* C = Cb;
    if (MODE >= 10 && MODE <= 12) {
        int cell = blockIdx.y; ci = i_min + cell; cj = d - ci;
        if (MODE == 10) { A = g_cwc + cj*RWS*DM; Bm = Bb + cj*DM*2*DI; C = g_xz  + cj*RWS*2*DI; }
        if (MODE == 11) { A = g_xc  + cj*RWS*DI; Bm = Bb + cj*DI*64;   C = g_xdbl+ cj*RWS*64;   }
        if (MODE == 12) { A = g_y   + cj*RWS*DI; Bm = Bb + cj*DI*DM;   }
    }
    if (MODE == 20) { A = g_mamba; Bm = g_WqT; C = g_q; }
    if (MODE == 21) { A = g_mem;   Bm = g_WkT; C = g_k; }
    if (MODE == 22) { A = g_mem;   Bm = g_WvT; C = g_v; }
    if (MODE == 23) { A = g_ao;    Bm = g_WoT; C = g_hres; }
    if (MODE == 24) { A = g_hf; }

    int tilesN = N >> 6;
    int mT = blockIdx.x / tilesN;
    int nT = blockIdx.x % tilesN;

    __shared__ float As[16][64];
    __shared__ float Bs[16][64];

    int tid = threadIdx.x;
    int ty = tid >> 4, tx = tid & 15;
    float acc[4][4];
    #pragma unroll
    for (int i2 = 0; i2 < 4; i2++)
        #pragma unroll
        for (int j2 = 0; j2 < 4; j2++) acc[i2][j2] = 0.f;

    int ar = tid >> 2, kq = tid & 3;
    int br = tid >> 4, nq = tid & 15;
    int grA = mT*64 + ar;
    const float* Aptr = A + (long)grA*K + kq*4;
    const float* Bptr = Bm + (long)br*N + nT*64 + nq*4;

    for (int k0 = 0; k0 < K; k0 += 16) {
        float4 av = make_float4(0.f,0.f,0.f,0.f);
        if (grA < M) av = *(const float4*)(Aptr + k0);
        float4 bv = *(const float4*)(Bptr + (long)k0*N);
        As[kq*4+0][ar] = av.x; As[kq*4+1][ar] = av.y;
        As[kq*4+2][ar] = av.z; As[kq*4+3][ar] = av.w;
        *(float4*)&Bs[br][nq*4] = bv;
        __syncthreads();
        #pragma unroll
        for (int kk = 0; kk < 16; kk++) {
            float4 a = *(float4*)&As[kk][ty*4];
            float4 b = *(float4*)&Bs[kk][tx*4];
            acc[0][0] += a.x*b.x; acc[0][1] += a.x*b.y; acc[0][2] += a.x*b.z; acc[0][3] += a.x*b.w;
            acc[1][0] += a.y*b.x; acc[1][1] += a.y*b.y; acc[1][2] += a.y*b.z; acc[1][3] += a.y*b.w;
            acc[2][0] += a.z*b.x; acc[2][1] += a.z*b.y; acc[2][2] += a.z*b.z; acc[2][3] += a.z*b.w;
            acc[3][0] += a.w*b.x; acc[3][1] += a.w*b.y; acc[3][2] += a.w*b.z; acc[3][3] += a.w*b.w;
        }
        __syncthreads();
    }

    #pragma unroll
    for (int ii = 0; ii < 4; ii++) {
        int gr = mT*64 + ty*4 + ii;
        if (gr >= M) continue;
        #pragma unroll
        for (int jj = 0; jj < 4; jj++) {
            int gc = nT*64 + tx*4 + jj;
            float v = acc[ii][jj];
            if (MODE == 10 || MODE == 11 || MODE == 24) {
                C[(long)gr*N + gc] = v;
            } else if (MODE == 20 || MODE == 21 || MODE == 22) {
                C[(long)gr*N + gc] = v + bias[gc];
            } else if (MODE == 23) {
                int l = gr & (LL-1);
                int tb = l >> 6;
                float v2 = (tb > 0) ? (v + bias[gc]) : 0.f;
                C[(long)gr*N + gc] = g_mamba[(long)gr*DM + gc] + v2;
            } else if (MODE == 12) {
                int b = gr / TT; int tt = gr - b*TT;
                if (tt > 0)
                    g_co[((ci*BB + b)*BLKT + (tt-1))*DM + gc] += v;
                if (tt == TT-1) {
                    g_state[((cj*2 + (ci&1))*BB + b)*DM + gc] = v;
                    if (cj == NLAY-1) g_mem[(b*NCH + ci)*DM + gc] = v;
                }
            }
        }
    }
}

// ---------------- tail kernels ----------------
__global__ void reorder_k() {
    int id = blockIdx.x*256 + threadIdx.x;          // BB*LL*DM
    int c = id & 511; int rest = id >> 9;
    int l = rest & 2047; int b = rest >> 11;
    int i = l >> 6; int t = l & 63;
    g_mamba[id] = g_co[((i*BB + b)*BLKT + t)*DM + c];
}

__global__ void attn_k() {
    int w = blockIdx.x*8 + (threadIdx.x >> 5);      // BB*LL*4 = 16384 warps
    int lane = threadIdx.x & 31;
    int b = w >> 13; int rem = w & 8191;
    int l = rem >> 2; int h = rem & 3;
    int tb = l >> 6;
    float* aoRow = g_ao + ((long)b*LL + l)*DM + h*128;
    if (tb == 0) {
        #pragma unroll
        for (int e = 0; e < 4; e++) aoRow[lane + 32*e] = 0.f;
        return;
    }
    const float* qr = g_q + ((long)b*LL + l)*DM + h*128;
    float sc = -1e30f;
    if (lane < tb) {
        const float* kr = g_k + (b*NCH + lane)*DM + h*128;
        float s = 0.f;
        #pragma unroll 4
        for (int kk = 0; kk < 128; kk++) s += qr[kk]*kr[kk];
        sc = s * 0.08838834764831845f;              // 1/sqrt(128)
    }
    float mx = sc;
    #pragma unroll
    for (int o = 16; o > 0; o >>= 1) mx = fmaxf(mx, __shfl_xor_sync(0xffffffffu, mx, o));
    float p = (lane < tb) ? __expf(sc - mx) : 0.f;
    float sum = p;
    #pragma unroll
    for (int o = 16; o > 0; o >>= 1) sum += __shfl_xor_sync(0xffffffffu, sum, o);
    float a = p / sum;
    float accv[4] = {0.f,0.f,0.f,0.f};
    for (int mm = 0; mm < tb; mm++) {
        float am = __shfl_sync(0xffffffffu, a, mm);
        const float* vr = g_v + (b*NCH + mm)*DM + h*128;
        #pragma unroll
        for (int e = 0; e < 4; e++) accv[e] += am * vr[lane + 32*e];
    }
    #pragma unroll
    for (int e = 0; e < 4; e++) aoRow[lane + 32*e] = accv[e];
}

__global__ void ln_k(const float* __restrict__ lw, const float* __restrict__ lb) {
    int r = blockIdx.x*4 + (threadIdx.x >> 5);      // BB*LL rows
    int lane = threadIdx.x & 31;
    const float* src = g_hres + (long)r*DM;
    float vals[16]; float s1 = 0.f, s2 = 0.f;
    #pragma unroll
    for (int k2 = 0; k2 < 16; k2++) { float v = src[lane + 32*k2]; vals[k2] = v; s1 += v; s2 += v*v; }
    #pragma unroll
    for (int o = 16; o > 0; o >>= 1) {
        s1 += __shfl_xor_sync(0xffffffffu, s1, o);
        s2 += __shfl_xor_sync(0xffffffffu, s2, o);
    }
    float mu = s1 * (1.0f/DM);
    float var = s2 * (1.0f/DM) - mu*mu;
    float is = rsqrtf(var + 1e-5f);
    #pragma unroll
    for (int k2 = 0; k2 < 16; k2++) {
        int c = lane + 32*k2;
        g_hf[(long)r*DM + c] = (vals[k2] - mu)*is*lw[c] + lb[c];
    }
}

// ---------------- launcher ----------------
extern "C" void kernel_launch(void* const* d_in, const int* in_sizes, int n_in,
                              void* d_out, int out_size) {
    const int*   tokens = (const int*)  d_in[0];
    const float* embed  = (const float*)d_in[1];
    const float* rms_w  = (const float*)d_in[2];
    const float* W_in   = (const float*)d_in[3];
    const float* conv_w = (const float*)d_in[4];
    const float* conv_b = (const float*)d_in[5];
    const float* x_proj = (const float*)d_in[6];
    const float* dt_w   = (const float*)d_in[7];
    const float* dt_b   = (const float*)d_in[8];
    const float* A_log  = (const float*)d_in[9];
    const float* D_skip = (const float*)d_in[10];
    const float* W_out  = (const float*)d_in[11];
    const float* init_state = (const float*)d_in[12];
    const float* Wq = (const float*)d_in[13];
    const float* Wk = (const float*)d_in[14];
    const float* Wv = (const float*)d_in[15];
    const float* bq = (const float*)d_in[16];
    const float* bk = (const float*)d_in[17];
    const float* bv = (const float*)d_in[18];
    const float* Wo = (const float*)d_in[19];
    const float* bo = (const float*)d_in[20];
    const float* ln_w = (const float*)d_in[21];
    const float* ln_b = (const float*)d_in[22];
    const float* head_w = (const float*)d_in[23];
    float* out = (float*)d_out;

    embed_k<<<8192, 256>>>(tokens, embed);
    a2_k  <<<960,  256>>>(A_log);
    trans_k<<<4096, 256>>>(Wq, Wk, Wv, Wo);
    sinit_k<<<60,   256>>>(init_state);

    // wavefront over diagonals d = chunk + layer
    for (int d = 0; d < NCH + NLAY - 1; d++) {
        int i_min = d - (NLAY - 1); if (i_min < 0) i_min = 0;
        int i_max = (d < NCH - 1) ? d : NCH - 1;
        int nc = i_max - i_min + 1;
        prep_k<<<(nc*RWS + 3)/4, 128>>>(d, i_min, nc*RWS, rms_w);
        gemm_k<10><<<dim3(96, nc), 256>>>(nullptr, W_in, nullptr, RWS, 2*DI, DM, nullptr, d, i_min);
        conv_k<<<dim3(520, nc), 256>>>(d, i_min, conv_w, conv_b);
        gemm_k<11><<<dim3(3, nc), 256>>>(nullptr, x_proj, nullptr, RWS, 64, DI, nullptr, d, i_min);
        scan_k<<<nc*16, 128>>>(d, i_min, dt_w, dt_b, D_skip);
        gemm_k<12><<<dim3(24, nc), 256>>>(nullptr, W_out, nullptr, RWS, DM, DI, nullptr, d, i_min);
    }

    reorder_k<<<8192, 256>>>();
    gemm_k<20><<<512, 256>>>(nullptr, nullptr, nullptr, BB*LL, DM, DM, bq, 0, 0);
    gemm_k<21><<<8,   256>>>(nullptr, nullptr, nullptr, BB*NCH, DM, DM, bk, 0, 0);
    gemm_k<22><<<8,   256>>>(nullptr, nullptr, nullptr, BB*NCH, DM, DM, bv, 0, 0);
    attn_k<<<2048, 256>>>();
    gemm_k<23><<<512, 256>>>(nullptr, nullptr, nullptr, BB*LL, DM, DM, bo, 0, 0);
    ln_k<<<1024, 128>>>(ln_w, ln_b);
    gemm_k<24><<<512, 256>>>(nullptr, head_w, out, BB*LL, DM, DM, nullptr, 0, 0);
}